// round 1
// baseline (speedup 1.0000x reference)
#include <cuda_runtime.h>
#include <math.h>

#define UNITS 1024
#define FEAT  1024
#define GCOLS 4096                 // 4 * UNITS gate columns
#define KSLICES 64
#define KCHUNK (FEAT / KSLICES)    // 16

// Scratch (device globals: no allocation allowed in kernel_launch)
__device__ float g_pxw0[KSLICES][GCOLS];   // partials of x0 @ W
__device__ float g_pxw1[KSLICES][GCOLS];   // partials of x1 @ W
__device__ float g_phu [KSLICES][GCOLS];   // partials of h0 @ U
__device__ float g_z1pre[GCOLS];           // x1@W + b
__device__ float g_h0[UNITS];
__device__ float g_c0[UNITS];

__device__ __forceinline__ float sigmoidf_(float x) {
    return 1.0f / (1.0f + expf(-x));
}

// ---------------------------------------------------------------------------
// Kernel 1: partial GEMV  z0_part = x[0,:] @ W,  z1_part = x[1,:] @ W
// grid = (4, KSLICES), block = 256 threads, each thread -> 4 consecutive cols
// W is (FEAT, 4096) row-major -> float4 loads fully coalesced across threads.
// ---------------------------------------------------------------------------
__global__ void k_xw(const float* __restrict__ x, const float* __restrict__ W) {
    const int j  = (blockIdx.x * 256 + threadIdx.x) * 4;   // column base
    const int k0 = blockIdx.y * KCHUNK;

    float4 a0 = make_float4(0.f, 0.f, 0.f, 0.f);
    float4 a1 = make_float4(0.f, 0.f, 0.f, 0.f);

    #pragma unroll
    for (int kk = 0; kk < KCHUNK; ++kk) {
        const int k = k0 + kk;
        const float4 w = *reinterpret_cast<const float4*>(W + (size_t)k * GCOLS + j);
        const float xa = __ldg(x + k);           // x[0, k]
        const float xb = __ldg(x + FEAT + k);    // x[1, k]
        a0.x += xa * w.x; a0.y += xa * w.y; a0.z += xa * w.z; a0.w += xa * w.w;
        a1.x += xb * w.x; a1.y += xb * w.y; a1.z += xb * w.z; a1.w += xb * w.w;
    }
    *reinterpret_cast<float4*>(&g_pxw0[blockIdx.y][j]) = a0;
    *reinterpret_cast<float4*>(&g_pxw1[blockIdx.y][j]) = a1;
}

// ---------------------------------------------------------------------------
// Kernel 2: reduce x@W partials (+b), compute t=0 gates -> h0, c0; stash z1pre
// One block of 1024 threads. Fixed-order (deterministic) reduction.
// ---------------------------------------------------------------------------
__global__ void k_gate0(const float* __restrict__ b) {
    __shared__ float sz0[GCOLS];
    const int tid = threadIdx.x;

    for (int j = tid; j < GCOLS; j += 1024) {
        const float bj = __ldg(b + j);
        float s0 = bj, s1 = bj;
        #pragma unroll
        for (int s = 0; s < KSLICES; ++s) {
            s0 += g_pxw0[s][j];
            s1 += g_pxw1[s][j];
        }
        sz0[j]     = s0;
        g_z1pre[j] = s1;
    }
    __syncthreads();

    // gate order [i, f, c(g), o]; c_prev = 0 so forget gate is irrelevant at t=0
    const int u = tid;                 // exactly 1024 threads
    const float zi = sz0[u];
    const float zg = sz0[2 * UNITS + u];
    const float zo = sz0[3 * UNITS + u];
    const float c  = sigmoidf_(zi) * zg;       // candidate activation = identity
    const float h  = sigmoidf_(zo) * c;        // output activation = identity
    g_c0[u] = c;
    g_h0[u] = h;
}

// ---------------------------------------------------------------------------
// Kernel 3: partial GEMV  z1u_part = h0 @ U  (same structure as k_xw)
// ---------------------------------------------------------------------------
__global__ void k_hu(const float* __restrict__ U) {
    const int j  = (blockIdx.x * 256 + threadIdx.x) * 4;
    const int k0 = blockIdx.y * KCHUNK;

    float4 a = make_float4(0.f, 0.f, 0.f, 0.f);

    #pragma unroll
    for (int kk = 0; kk < KCHUNK; ++kk) {
        const int k = k0 + kk;
        const float4 u4 = *reinterpret_cast<const float4*>(U + (size_t)k * GCOLS + j);
        const float h = g_h0[k];
        a.x += h * u4.x; a.y += h * u4.y; a.z += h * u4.z; a.w += h * u4.w;
    }
    *reinterpret_cast<float4*>(&g_phu[blockIdx.y][j]) = a;
}

// ---------------------------------------------------------------------------
// Kernel 4: reduce z1, t=1 gates -> h1; dense head; finite difference; output.
// One block of 1024 threads.
// ---------------------------------------------------------------------------
__global__ void k_final(const float* __restrict__ f,
                        const float* __restrict__ Wd,
                        const float* __restrict__ bd,
                        float* __restrict__ out) {
    __shared__ float sz[GCOLS];
    __shared__ float red[4][32];
    const int tid = threadIdx.x;

    for (int j = tid; j < GCOLS; j += 1024) {
        float s = g_z1pre[j];
        #pragma unroll
        for (int sI = 0; sI < KSLICES; ++sI) s += g_phu[sI][j];
        sz[j] = s;
    }
    __syncthreads();

    const int u = tid;
    const float c0 = g_c0[u];
    const float h0 = g_h0[u];

    const float i1 = sigmoidf_(sz[u]);
    const float f1 = sigmoidf_(sz[UNITS + u]);
    const float o1 = sigmoidf_(sz[3 * UNITS + u]);
    const float c1 = f1 * c0 + i1 * sz[2 * UNITS + u];
    const float h1 = o1 * c1;

    const float n0 = tanhf(h0);
    const float n1 = tanhf(h1);

    const float wd0 = __ldg(Wd + 2 * u);
    const float wd1 = __ldg(Wd + 2 * u + 1);
    float v0 = n0 * wd0;   // -> h_c0[0]
    float v1 = n0 * wd1;   // -> h_c0[1]
    float v2 = n1 * wd0;   // -> h_c1[0]
    float v3 = n1 * wd1;   // -> h_c1[1]

    // warp-level tree reduce (deterministic), then cross-warp via shared
    #pragma unroll
    for (int off = 16; off > 0; off >>= 1) {
        v0 += __shfl_down_sync(0xffffffffu, v0, off);
        v1 += __shfl_down_sync(0xffffffffu, v1, off);
        v2 += __shfl_down_sync(0xffffffffu, v2, off);
        v3 += __shfl_down_sync(0xffffffffu, v3, off);
    }
    const int lane = tid & 31;
    const int wrp  = tid >> 5;
    if (lane == 0) {
        red[0][wrp] = v0; red[1][wrp] = v1; red[2][wrp] = v2; red[3][wrp] = v3;
    }
    __syncthreads();

    if (wrp == 0) {
        float r0 = red[0][lane];
        float r1 = red[1][lane];
        float r2 = red[2][lane];
        float r3 = red[3][lane];
        #pragma unroll
        for (int off = 16; off > 0; off >>= 1) {
            r0 += __shfl_down_sync(0xffffffffu, r0, off);
            r1 += __shfl_down_sync(0xffffffffu, r1, off);
            r2 += __shfl_down_sync(0xffffffffu, r2, off);
            r3 += __shfl_down_sync(0xffffffffu, r3, off);
        }
        if (lane == 0) {
            const float b0 = __ldg(bd + 0);
            const float b1 = __ldg(bd + 1);
            const float hc00 = tanhf(r0 + b0);   // h_c[0,0]
            const float hc01 = tanhf(r1 + b1);   // h_c[0,1]
            const float hc10 = tanhf(r2 + b0);   // h_c[1,0]
            const float hc11 = tanhf(r3 + b1);   // h_c[1,1]
            const float den  = __ldg(f + 1) - __ldg(f + 2);
            out[0] = hc00;                       // h_out
            out[1] = hc01;
            out[2] = (hc00 - hc10) / den;        // H
            out[3] = (hc01 - hc11) / den;
        }
    }
}

// ---------------------------------------------------------------------------
extern "C" void kernel_launch(void* const* d_in, const int* in_sizes, int n_in,
                              void* d_out, int out_size) {
    (void)in_sizes; (void)n_in; (void)out_size;
    const float* x  = (const float*)d_in[0];   // inputs (1, 8192, 1024)
    const float* f  = (const float*)d_in[1];   // f (8192, 1)
    const float* W  = (const float*)d_in[2];   // (1024, 4096)
    const float* U  = (const float*)d_in[3];   // (1024, 4096)
    const float* b  = (const float*)d_in[4];   // (4096,)
    const float* Wd = (const float*)d_in[5];   // (1024, 2)
    const float* bd = (const float*)d_in[6];   // (2,)
    float* out = (float*)d_out;

    dim3 gemv_grid(GCOLS / (256 * 4), KSLICES);   // (4, 64)
    k_xw   <<<gemv_grid, 256>>>(x, W);
    k_gate0<<<1, 1024>>>(b);
    k_hu   <<<gemv_grid, 256>>>(U);
    k_final<<<1, 1024>>>(f, Wd, bd, out);
}

// round 2
// speedup vs baseline: 1.8206x; 1.8206x over previous
#include <cuda_runtime.h>
#include <math.h>

#define UNITS 1024
#define FEAT  1024
#define GCOLS 4096                 // 4 * UNITS gate columns
#define KSLICES 64
#define KCHUNK (FEAT / KSLICES)    // 16
#define RBLOCKS 16                 // reduce/gate blocks (16 x 256 = 4096 threads)

// Scratch (device globals: no allocation allowed in kernel_launch)
__device__ float g_pxw0[KSLICES][GCOLS];   // partials of x0 @ W
__device__ float g_pxw1[KSLICES][GCOLS];   // partials of x1 @ W
__device__ float g_phu [KSLICES][GCOLS];   // partials of h0 @ U
__device__ float g_z1pre[GCOLS];           // x1@W + b
__device__ float g_h0[UNITS];
__device__ float g_c0[UNITS];
__device__ float g_dot[RBLOCKS][4];        // per-block partial dense dots

__device__ __forceinline__ float sigmoidf_(float x) {
    return 1.0f / (1.0f + expf(-x));
}

// ---------------------------------------------------------------------------
// Kernel 1: partial GEMV  z0_part = x[0,:] @ W,  z1_part = x[1,:] @ W
// grid = (4, KSLICES) = 256 blocks, 256 threads, thread -> 4 consecutive cols
// ---------------------------------------------------------------------------
__global__ void k_xw(const float* __restrict__ x, const float* __restrict__ W) {
    const int j  = (blockIdx.x * 256 + threadIdx.x) * 4;   // column base
    const int k0 = blockIdx.y * KCHUNK;

    float4 a0 = make_float4(0.f, 0.f, 0.f, 0.f);
    float4 a1 = make_float4(0.f, 0.f, 0.f, 0.f);

    #pragma unroll
    for (int kk = 0; kk < KCHUNK; ++kk) {
        const int k = k0 + kk;
        const float4 w = *reinterpret_cast<const float4*>(W + (size_t)k * GCOLS + j);
        const float xa = __ldg(x + k);           // x[0, k]
        const float xb = __ldg(x + FEAT + k);    // x[1, k]
        a0.x += xa * w.x; a0.y += xa * w.y; a0.z += xa * w.z; a0.w += xa * w.w;
        a1.x += xb * w.x; a1.y += xb * w.y; a1.z += xb * w.z; a1.w += xb * w.w;
    }
    *reinterpret_cast<float4*>(&g_pxw0[blockIdx.y][j]) = a0;
    *reinterpret_cast<float4*>(&g_pxw1[blockIdx.y][j]) = a1;
}

// ---------------------------------------------------------------------------
// Kernel 2: distributed reduce of x@W partials + t=0 gate math.
// 16 blocks x 256 threads = 4096 threads; thread (u, q) owns gate column
// col = u + q*1024. Sums 64 slices (warp touches 4 fully-used 32B sectors per
// load), writes z1pre[col], then gathers the 4 gate values of unit u via 3
// shuffles; lane q==0 computes h0, c0. Fully deterministic.
// ---------------------------------------------------------------------------
__global__ void k_gate0(const float* __restrict__ b) {
    const int g    = blockIdx.x * 256 + threadIdx.x;  // 0..4095
    const int u    = g >> 2;
    const int q    = g & 3;
    const int col  = u + (q << 10);

    float s0 = 0.f, s1 = 0.f;
    #pragma unroll 16
    for (int s = 0; s < KSLICES; ++s) {
        s0 += g_pxw0[s][col];
        s1 += g_pxw1[s][col];
    }
    const float bc = __ldg(b + col);
    const float z0 = s0 + bc;
    g_z1pre[col] = s1 + bc;

    const unsigned m = 0xffffffffu;
    const int lane = threadIdx.x & 31;
    const int base = lane & ~3;
    const float zi = __shfl_sync(m, z0, base + 0);
    const float zg = __shfl_sync(m, z0, base + 2);
    const float zo = __shfl_sync(m, z0, base + 3);
    if (q == 0) {
        const float c = sigmoidf_(zi) * zg;   // c_prev = 0, candidate act = id
        const float h = sigmoidf_(zo) * c;    // output act = id
        g_c0[u] = c;
        g_h0[u] = h;
    }
}

// ---------------------------------------------------------------------------
// Kernel 3: partial GEMV  z1u_part = h0 @ U
// ---------------------------------------------------------------------------
__global__ void k_hu(const float* __restrict__ U) {
    const int j  = (blockIdx.x * 256 + threadIdx.x) * 4;
    const int k0 = blockIdx.y * KCHUNK;

    float4 a = make_float4(0.f, 0.f, 0.f, 0.f);

    #pragma unroll
    for (int kk = 0; kk < KCHUNK; ++kk) {
        const int k = k0 + kk;
        const float4 u4 = *reinterpret_cast<const float4*>(U + (size_t)k * GCOLS + j);
        const float h = g_h0[k];
        a.x += h * u4.x; a.y += h * u4.y; a.z += h * u4.z; a.w += h * u4.w;
    }
    *reinterpret_cast<float4*>(&g_phu[blockIdx.y][j]) = a;
}

// ---------------------------------------------------------------------------
// Kernel 4: distributed reduce of h0@U partials + t=1 gate math + per-block
// partial dense-head dots. Same thread layout as k_gate0.
// ---------------------------------------------------------------------------
__global__ void k_final1(const float* __restrict__ Wd) {
    __shared__ float red[4][8];
    const int g   = blockIdx.x * 256 + threadIdx.x;
    const int u   = g >> 2;
    const int q   = g & 3;
    const int col = u + (q << 10);

    float s = 0.f;
    #pragma unroll 16
    for (int sl = 0; sl < KSLICES; ++sl) s += g_phu[sl][col];
    const float z1 = s + g_z1pre[col];

    const unsigned m = 0xffffffffu;
    const int lane = threadIdx.x & 31;
    const int wrp  = threadIdx.x >> 5;
    const int base = lane & ~3;
    const float zi = __shfl_sync(m, z1, base + 0);
    const float zf = __shfl_sync(m, z1, base + 1);
    const float zg = __shfl_sync(m, z1, base + 2);
    const float zo = __shfl_sync(m, z1, base + 3);

    float v0 = 0.f, v1 = 0.f, v2 = 0.f, v3 = 0.f;
    if (q == 0) {
        const float c1 = sigmoidf_(zf) * g_c0[u] + sigmoidf_(zi) * zg;
        const float h1 = sigmoidf_(zo) * c1;
        const float n0 = tanhf(g_h0[u]);
        const float n1 = tanhf(h1);
        const float wd0 = __ldg(Wd + 2 * u);
        const float wd1 = __ldg(Wd + 2 * u + 1);
        v0 = n0 * wd0;   // -> h_c[0,0]
        v1 = n0 * wd1;   // -> h_c[0,1]
        v2 = n1 * wd0;   // -> h_c[1,0]
        v3 = n1 * wd1;   // -> h_c[1,1]
    }
    // deterministic block reduce (non-q0 lanes contribute exact zeros)
    #pragma unroll
    for (int off = 16; off > 0; off >>= 1) {
        v0 += __shfl_down_sync(m, v0, off);
        v1 += __shfl_down_sync(m, v1, off);
        v2 += __shfl_down_sync(m, v2, off);
        v3 += __shfl_down_sync(m, v3, off);
    }
    if (lane == 0) {
        red[0][wrp] = v0; red[1][wrp] = v1; red[2][wrp] = v2; red[3][wrp] = v3;
    }
    __syncthreads();
    if (wrp == 0) {
        float r0 = (lane < 8) ? red[0][lane] : 0.f;
        float r1 = (lane < 8) ? red[1][lane] : 0.f;
        float r2 = (lane < 8) ? red[2][lane] : 0.f;
        float r3 = (lane < 8) ? red[3][lane] : 0.f;
        #pragma unroll
        for (int off = 4; off > 0; off >>= 1) {
            r0 += __shfl_down_sync(m, r0, off);
            r1 += __shfl_down_sync(m, r1, off);
            r2 += __shfl_down_sync(m, r2, off);
            r3 += __shfl_down_sync(m, r3, off);
        }
        if (lane == 0) {
            g_dot[blockIdx.x][0] = r0;
            g_dot[blockIdx.x][1] = r1;
            g_dot[blockIdx.x][2] = r2;
            g_dot[blockIdx.x][3] = r3;
        }
    }
}

// ---------------------------------------------------------------------------
// Kernel 5: fold the 16 per-block dot partials, apply bias/tanh/finite-diff.
// ---------------------------------------------------------------------------
__global__ void k_final2(const float* __restrict__ f,
                         const float* __restrict__ bd,
                         float* __restrict__ out) {
    const unsigned m = 0xffffffffu;
    const int lane = threadIdx.x;   // 32 threads
    float r0 = (lane < RBLOCKS) ? g_dot[lane][0] : 0.f;
    float r1 = (lane < RBLOCKS) ? g_dot[lane][1] : 0.f;
    float r2 = (lane < RBLOCKS) ? g_dot[lane][2] : 0.f;
    float r3 = (lane < RBLOCKS) ? g_dot[lane][3] : 0.f;
    #pragma unroll
    for (int off = 8; off > 0; off >>= 1) {
        r0 += __shfl_down_sync(m, r0, off);
        r1 += __shfl_down_sync(m, r1, off);
        r2 += __shfl_down_sync(m, r2, off);
        r3 += __shfl_down_sync(m, r3, off);
    }
    if (lane == 0) {
        const float b0 = __ldg(bd + 0);
        const float b1 = __ldg(bd + 1);
        const float hc00 = tanhf(r0 + b0);   // h_c[0,0]
        const float hc01 = tanhf(r1 + b1);   // h_c[0,1]
        const float hc10 = tanhf(r2 + b0);   // h_c[1,0]
        const float hc11 = tanhf(r3 + b1);   // h_c[1,1]
        const float den  = __ldg(f + 1) - __ldg(f + 2);
        out[0] = hc00;                       // h_out
        out[1] = hc01;
        out[2] = (hc00 - hc10) / den;        // H
        out[3] = (hc01 - hc11) / den;
    }
}

// ---------------------------------------------------------------------------
extern "C" void kernel_launch(void* const* d_in, const int* in_sizes, int n_in,
                              void* d_out, int out_size) {
    (void)in_sizes; (void)n_in; (void)out_size;
    const float* x  = (const float*)d_in[0];   // inputs (1, 8192, 1024)
    const float* f  = (const float*)d_in[1];   // f (8192, 1)
    const float* W  = (const float*)d_in[2];   // (1024, 4096)
    const float* U  = (const float*)d_in[3];   // (1024, 4096)
    const float* b  = (const float*)d_in[4];   // (4096,)
    const float* Wd = (const float*)d_in[5];   // (1024, 2)
    const float* bd = (const float*)d_in[6];   // (2,)
    float* out = (float*)d_out;

    dim3 gemv_grid(GCOLS / (256 * 4), KSLICES);   // (4, 64)
    k_xw    <<<gemv_grid, 256>>>(x, W);
    k_gate0 <<<RBLOCKS, 256>>>(b);
    k_hu    <<<gemv_grid, 256>>>(U);
    k_final1<<<RBLOCKS, 256>>>(Wd);
    k_final2<<<1, 32>>>(f, bd, out);
}